// round 10
// baseline (speedup 1.0000x reference)
#include <cuda_runtime.h>
#include <math.h>

// ---------------------------------------------------------------------------
// Problem constants (fixed by setup_inputs)
// ---------------------------------------------------------------------------
#define NB    8
#define HH    64
#define WW    64
#define CIN   512
#define COUT  512
#define PIX   4096          // HH*WW
#define NANC  9
#define MTOT  36864         // PIX*NANC
#define SEG   65536         // sort segment (padded)
#define PRE   2000
#define POST  300

// output packing (concatenated float32, return order of reference())
#define O_LOCS   0                    // 8*36864*4  = 1179648
#define O_SCORES 1179648              // 8*36864*2  =  589824
#define O_ROIS   1769472              // 8*300*4    =    9600
#define O_IDX    1779072              // 8*300      =    2400
#define O_ANCH   1781472              // 36864*4    =  147456

// Correctly-rounded fp32 exp (immune to fast-math substitution).
__device__ __forceinline__ float exact_expf(float x) {
    return (float)exp((double)x);
}

// ---------------------------------------------------------------------------
// Device scratch (static -> allocation-free)
// ---------------------------------------------------------------------------
__device__ float              g_h[NB * COUT * PIX];        // 64 MB conv output
__device__ float              g_wT[9 * CIN * COUT];        // transposed weights [k][c][o]
__device__ float              g_fg[NB * MTOT];             // fg scores
__device__ float              g_boxes[NB * MTOT * 4];      // decoded boxes
__device__ unsigned long long g_keys[NB * SEG];            // sort keys
__device__ float              g_tb[NB * PRE * 4];          // top-2000 boxes
__device__ unsigned char      g_tvalid[NB * PRE];
__device__ unsigned           g_mask[NB * PRE * 64];       // NMS bitmask rows

// ---------------------------------------------------------------------------
// Weight transpose: wT[k][c][o] = w[o][c][k]. Coalesced writes; ~20us.
// ---------------------------------------------------------------------------
__global__ void wtrans_k(const float* __restrict__ w) {
    long t = (long)blockIdx.x * 256 + threadIdx.x;     // 9*512*512 threads
    int k   = (int)(t / (CIN * COUT));
    int rem = (int)(t - (long)k * CIN * COUT);
    int c   = rem >> 9;
    int o   = rem & 511;
    g_wT[t] = w[(long)o * 4608 + c * 9 + k];
}

// ---------------------------------------------------------------------------
// 3x3 conv (512->512, pad 1) + bias + ReLU, fp32.
// NUMERICS FROZEN (matches R8/R9 bitwise): per-output single fp32 accumulator,
// __fmaf_rn chain strictly ordered (ky, kx, c ascending).
// Block: 256 out-channels x 64 pixels (one row). 256 threads, 8x8 reg tile.
// smem bytes/FMA = 1.0 (4 LDS.128 per 64 FMA) -> issue/FMA-bound, not crossbar.
// ---------------------------------------------------------------------------
#define CCH 32
__global__ void __launch_bounds__(256, 2) conv3x3_k(const float* __restrict__ x,
                                                    const float* __restrict__ bias) {
    __shared__ float xs[CCH][68];        // input row slice for current (ky,kx)
    __shared__ float ws[CCH][264];       // [c][outch 0..255], padded row (16B-mult)

    const int rt  = blockIdx.y;          // n*64 + y
    const int n   = rt >> 6;
    const int y   = rt & 63;
    const int ko0 = blockIdx.x << 8;     // 256 outch per block (grid.x = 2)
    const int tid = threadIdx.x;
    const int tp  = tid & 7;             // pixel group  (px0 = tp*8)
    const int to  = tid >> 3;            // outch group  (o0 = to*8)
    const int px0 = tp << 3;
    const int o0  = to << 3;

    float acc[8][8];                     // [o][p]
#pragma unroll
    for (int a = 0; a < 8; a++)
#pragma unroll
        for (int b = 0; b < 8; b++) acc[a][b] = 0.f;

    const float* xb = x + (long)n * CIN * PIX;

    for (int ky = 0; ky < 3; ky++) {
        int yy = y - 1 + ky;
        bool rowok = (yy >= 0 && yy < 64);
        const float* xrow = xb + yy * 64;
        for (int kx = 0; kx < 3; kx++) {
            const float* wk = g_wT + (ky * 3 + kx) * (CIN * COUT) + ko0;
            for (int c0 = 0; c0 < CIN; c0 += CCH) {
                // stage x: xs[cc][p] = x[c0+cc][yy][p+kx-1] (zero OOB)
                for (int idx = tid; idx < CCH * 64; idx += 256) {
                    int cc = idx >> 6;
                    int p  = idx & 63;
                    int xx = p + kx - 1;
                    float v = 0.f;
                    if (rowok && xx >= 0 && xx < 64)
                        v = xrow[(c0 + cc) * PIX + xx];
                    xs[cc][p] = v;
                }
                // stage w (coalesced float4 from transposed layout): 32c x 256o
                for (int idx = tid; idx < CCH * 64; idx += 256) {
                    int cc = idx >> 6;
                    int o4 = (idx & 63) << 2;
                    float4 wv = *(const float4*)&wk[(c0 + cc) * COUT + o4];
                    *(float4*)&ws[cc][o4] = wv;
                }
                __syncthreads();

#pragma unroll 8
                for (int cc = 0; cc < CCH; cc++) {
                    float4 xv0 = *(const float4*)&xs[cc][px0];
                    float4 xv1 = *(const float4*)&xs[cc][px0 + 4];
                    float4 wv0 = *(const float4*)&ws[cc][o0];
                    float4 wv1 = *(const float4*)&ws[cc][o0 + 4];
                    float xa[8] = {xv0.x, xv0.y, xv0.z, xv0.w,
                                   xv1.x, xv1.y, xv1.z, xv1.w};
                    float wv[8] = {wv0.x, wv0.y, wv0.z, wv0.w,
                                   wv1.x, wv1.y, wv1.z, wv1.w};
#pragma unroll
                    for (int o = 0; o < 8; o++)
#pragma unroll
                        for (int p = 0; p < 8; p++)
                            acc[o][p] = __fmaf_rn(wv[o], xa[p], acc[o][p]);
                }
                __syncthreads();
            }
        }
    }

#pragma unroll
    for (int s = 0; s < 8; s++) {
        int ko = ko0 + o0 + s;
        float bb = bias[ko];
        float* dst = &g_h[((n * COUT + ko) * HH + y) * WW + px0];
        float4 r0, r1;
        r0.x = fmaxf(__fadd_rn(acc[s][0], bb), 0.f);
        r0.y = fmaxf(__fadd_rn(acc[s][1], bb), 0.f);
        r0.z = fmaxf(__fadd_rn(acc[s][2], bb), 0.f);
        r0.w = fmaxf(__fadd_rn(acc[s][3], bb), 0.f);
        r1.x = fmaxf(__fadd_rn(acc[s][4], bb), 0.f);
        r1.y = fmaxf(__fadd_rn(acc[s][5], bb), 0.f);
        r1.z = fmaxf(__fadd_rn(acc[s][6], bb), 0.f);
        r1.w = fmaxf(__fadd_rn(acc[s][7], bb), 0.f);
        *(float4*)dst = r0;
        *(float4*)(dst + 4) = r1;
    }
}

// ---------------------------------------------------------------------------
// 1x1 heads: serial fp32 FMA over c ascending (NUMERICS FROZEN).
// ---------------------------------------------------------------------------
__global__ void __launch_bounds__(256) heads_k(const float* __restrict__ wsc,
                                               const float* __restrict__ bsc,
                                               const float* __restrict__ wlc,
                                               const float* __restrict__ blc,
                                               float* __restrict__ out) {
    const int bid  = blockIdx.x;         // 8*64*2 = 1024 blocks
    const int n    = bid >> 7;
    const int rem  = bid & 127;
    const int y    = rem >> 1;
    const int x0   = (rem & 1) << 5;
    const int lane = threadIdx.x & 31;
    const int wi   = threadIdx.x >> 5;
    const int ob   = wi * 7;

    float acc[7];
#pragma unroll
    for (int k = 0; k < 7; k++) acc[k] = 0.f;

    const float* hp = g_h + ((long)n * CIN * HH + y) * WW + x0 + lane;
    for (int c = 0; c < CIN; c++) {
        float hv = hp[c * PIX];
#pragma unroll
        for (int k = 0; k < 7; k++) {
            int o = ob + k;
            if (o < 54) {
                float wv = (o < 18) ? wsc[o * 512 + c] : wlc[(o - 18) * 512 + c];
                acc[k] = __fmaf_rn(hv, wv, acc[k]);
            }
        }
    }
    int pix = (n * 64 + y) * 64 + x0 + lane;
#pragma unroll
    for (int k = 0; k < 7; k++) {
        int o = ob + k;
        if (o >= 54) break;
        if (o < 18) out[O_SCORES + (long)pix * 18 + o]        = __fadd_rn(acc[k], bsc[o]);
        else        out[O_LOCS   + (long)pix * 36 + (o - 18)] = __fadd_rn(acc[k], blc[o - 18]);
    }
}

// softmax over score pairs -> fg score
__global__ void fg_k(const float* __restrict__ out) {
    int t = blockIdx.x * 256 + threadIdx.x;
    float s0 = out[O_SCORES + (long)t * 2];
    float s1 = out[O_SCORES + (long)t * 2 + 1];
    float m  = fmaxf(s0, s1);
    float e0 = exact_expf(__fsub_rn(s0, m));
    float e1 = exact_expf(__fsub_rn(s1, m));
    g_fg[t]  = __fdiv_rn(e1, __fadd_rn(e0, e1));
}

// ---------------------------------------------------------------------------
// anchors + box decode + clip + min-size mask + sort-key build
// meshgrid 'ij' transpose: yshift=(p%64)*16, xshift=(p/64)*16
// ---------------------------------------------------------------------------
__global__ void decode_k(float* __restrict__ out, const int* __restrict__ pih,
                         const int* __restrict__ piw) {
    int t = blockIdx.x * 256 + threadIdx.x;
    int b = t >> 16;
    int i = t & (SEG - 1);
    if (i >= MTOT) { g_keys[t] = 0xFFFFFFFFFFFFFFFFull; return; }

    int m   = i;
    int pxl = m / 9;
    int a   = m - pxl * 9;
    float ys  = (float)((pxl & 63) * 16);
    float xsh = (float)((pxl >> 6) * 16);

    const double RR[3] = {0.5, 1.0, 2.0};
    const double SS[3] = {8.0, 16.0, 32.0};
    int ridx = a / 3, sidx = a - ridx * 3;
    double hh = 16.0 * SS[sidx] * sqrt(RR[ridx]);
    double ww = 16.0 * SS[sidx] * sqrt(1.0 / RR[ridx]);
    float ay1 = (float)(8.0 - hh * 0.5);
    float ax1 = (float)(8.0 - ww * 0.5);
    float ay2 = (float)(8.0 + hh * 0.5);
    float ax2 = (float)(8.0 + ww * 0.5);

    float A0 = __fadd_rn(ay1, ys), A1 = __fadd_rn(ax1, xsh);
    float A2 = __fadd_rn(ay2, ys), A3 = __fadd_rn(ax2, xsh);
    if (b == 0) {
        float4 av = make_float4(A0, A1, A2, A3);
        *(float4*)&out[O_ANCH + (long)m * 4] = av;
    }

    float4 L = *(const float4*)&out[O_LOCS + ((long)b * MTOT + m) * 4];
    float ah  = __fsub_rn(A2, A0);
    float aw  = __fsub_rn(A3, A1);
    float acy = __fadd_rn(A0, __fmul_rn(0.5f, ah));
    float acx = __fadd_rn(A1, __fmul_rn(0.5f, aw));
    float cy  = __fadd_rn(__fmul_rn(L.x, ah), acy);
    float cx  = __fadd_rn(__fmul_rn(L.y, aw), acx);
    float bh  = __fmul_rn(exact_expf(L.z), ah);
    float bw  = __fmul_rn(exact_expf(L.w), aw);

    int vih = pih[0], viw = piw[0];
    float fh = (vih > 0 && vih < (1 << 20)) ? (float)vih : __int_as_float(vih);
    float fw = (viw > 0 && viw < (1 << 20)) ? (float)viw : __int_as_float(viw);

    float y1 = fminf(fmaxf(__fsub_rn(cy, __fmul_rn(0.5f, bh)), 0.f), fh);
    float x1 = fminf(fmaxf(__fsub_rn(cx, __fmul_rn(0.5f, bw)), 0.f), fw);
    float y2 = fminf(fmaxf(__fadd_rn(cy, __fmul_rn(0.5f, bh)), 0.f), fh);
    float x2 = fminf(fmaxf(__fadd_rn(cx, __fmul_rn(0.5f, bw)), 0.f), fw);
    float4 bx = make_float4(y1, x1, y2, x2);
    *(float4*)&g_boxes[((long)b * MTOT + m) * 4] = bx;

    float hs  = __fsub_rn(y2, y1);
    float wsz = __fsub_rn(x2, x1);
    bool valid = (hs >= 16.f) && (wsz >= 16.f);
    unsigned dk;
    if (valid) {
        float sc = g_fg[b * MTOT + m];
        unsigned ub  = __float_as_uint(sc);
        unsigned asc = (ub & 0x80000000u) ? ~ub : (ub | 0x80000000u);
        dk = ~asc;
    } else {
        dk = 0xFF800000u;
    }
    g_keys[t] = ((unsigned long long)dk << 32) | (unsigned)m;
}

// ---------------------------------------------------------------------------
// bitonic sort of 8 segments of 65536 u64 keys, ascending
// ---------------------------------------------------------------------------
__global__ void __launch_bounds__(1024) bitonic_presort_k() {
    __shared__ unsigned long long s[2048];
    int  t     = threadIdx.x;
    long base  = (long)blockIdx.x * 2048;
    int  lbase = (blockIdx.x & 31) * 2048;
    s[t] = g_keys[base + t];
    s[t + 1024] = g_keys[base + t + 1024];
    __syncthreads();
    for (int size = 2; size <= 2048; size <<= 1) {
        for (int stride = size >> 1; stride > 0; stride >>= 1) {
            int pos = 2 * t - (t & (stride - 1));
            bool asc = (((lbase + pos) & size) == 0);
            unsigned long long a = s[pos], b = s[pos + stride];
            if ((a > b) == asc) { s[pos] = b; s[pos + stride] = a; }
            __syncthreads();
        }
    }
    g_keys[base + t] = s[t];
    g_keys[base + t + 1024] = s[t + 1024];
}

__global__ void bitonic_global_k(int size, int stride) {
    int t   = blockIdx.x * 256 + threadIdx.x;
    int seg = t >> 15;
    int lt  = t & 32767;
    int pos = 2 * lt - (lt & (stride - 1));
    long i  = ((long)seg << 16) + pos;
    long j  = i + stride;
    bool asc = ((pos & size) == 0);
    unsigned long long a = g_keys[i], b = g_keys[j];
    if ((a > b) == asc) { g_keys[i] = b; g_keys[j] = a; }
}

__global__ void __launch_bounds__(1024) bitonic_finish_k(int size) {
    __shared__ unsigned long long s[2048];
    int  t     = threadIdx.x;
    long base  = (long)blockIdx.x * 2048;
    int  lbase = (blockIdx.x & 31) * 2048;
    bool asc   = ((lbase & size) == 0);
    s[t] = g_keys[base + t];
    s[t + 1024] = g_keys[base + t + 1024];
    __syncthreads();
    for (int stride = 1024; stride > 0; stride >>= 1) {
        int pos = 2 * t - (t & (stride - 1));
        unsigned long long a = s[pos], b = s[pos + stride];
        if ((a > b) == asc) { s[pos] = b; s[pos + stride] = a; }
        __syncthreads();
    }
    g_keys[base + t] = s[t];
    g_keys[base + t + 1024] = s[t + 1024];
}

// gather top-2000 per batch
__global__ void gather_k() {
    int t = blockIdx.x * 256 + threadIdx.x;
    int b = t >> 11;
    int i = t & 2047;
    if (i >= PRE) return;
    unsigned long long key = g_keys[b * SEG + i];
    unsigned idx = (unsigned)(key & 0xFFFFFFFFull);
    bool valid   = (unsigned)(key >> 32) < 0xFF800000u;
    float4 bx = *(const float4*)&g_boxes[((long)b * MTOT + idx) * 4];
    *(float4*)&g_tb[((long)b * PRE + i) * 4] = bx;
    g_tvalid[b * PRE + i] = valid ? 1 : 0;
}

// NMS bitmask: one warp per (b, i) (unfused IEEE fp32 IoU)
__global__ void nms_mask_k() {
    int wid  = blockIdx.x * 4 + (threadIdx.x >> 5);
    int lane = threadIdx.x & 31;
    int b = wid / PRE;
    int i = wid - b * PRE;
    float4 bi = *(const float4*)&g_tb[((long)b * PRE + i) * 4];
    float ai = __fmul_rn(__fsub_rn(bi.z, bi.x), __fsub_rn(bi.w, bi.y));
    unsigned* mrow = g_mask + ((long)b * PRE + i) * 64;
    for (int w = 0; w < 63; w++) {
        int j = w * 32 + lane;
        bool pred = false;
        if (j < PRE) {
            float4 bj = *(const float4*)&g_tb[((long)b * PRE + j) * 4];
            float aj = __fmul_rn(__fsub_rn(bj.z, bj.x), __fsub_rn(bj.w, bj.y));
            float ty = fmaxf(bi.x, bj.x), tx = fmaxf(bi.y, bj.y);
            float by = fminf(bi.z, bj.z), bx = fminf(bi.w, bj.w);
            float ihh = fmaxf(__fsub_rn(by, ty), 0.f);
            float iww = fmaxf(__fsub_rn(bx, tx), 0.f);
            float inter = __fmul_rn(ihh, iww);
            float denom = __fadd_rn(__fsub_rn(__fadd_rn(ai, aj), inter), 1e-10f);
            float iou = __fdiv_rn(inter, denom);
            pred = iou > 0.7f;
        }
        unsigned mword = __ballot_sync(0xFFFFFFFFu, pred);
        if (lane == 0) mrow[w] = mword;
    }
    if (lane == 0) mrow[63] = 0u;
}

// sequential greedy NMS scan (one warp per batch) + output rois/indices
__global__ void nms_scan_k(float* __restrict__ out) {
    int b = blockIdx.x;
    int lane = threadIdx.x;
    __shared__ unsigned rem[64];
    __shared__ int keptS[POST];
    __shared__ int nkS;
    rem[lane] = 0u; rem[lane + 32] = 0u;
    if (lane == 0) nkS = 0;
    __syncwarp();

    const unsigned char* valid = g_tvalid + b * PRE;
    const unsigned* maskb = g_mask + (long)b * PRE * 64;
    int nk = 0;
    for (int i = 0; i < PRE; i++) {
        int keep = 0;
        if (lane == 0)
            keep = valid[i] && !((rem[i >> 5] >> (i & 31)) & 1u);
        keep = __shfl_sync(0xFFFFFFFFu, keep, 0);
        if (keep) {
            if (lane == 0) keptS[nk] = i;
            nk++;
            if (nk >= POST) break;
            rem[2 * lane]     |= maskb[i * 64 + 2 * lane];
            rem[2 * lane + 1] |= maskb[i * 64 + 2 * lane + 1];
            __syncwarp();
        }
    }
    if (lane == 0) nkS = nk;
    __syncwarp();
    nk = nkS;
    for (int s = lane; s < POST; s += 32) {
        float4 v = make_float4(0.f, 0.f, 0.f, 0.f);
        if (s < nk) {
            int ii = keptS[s];
            v = *(const float4*)&g_tb[((long)b * PRE + ii) * 4];
        }
        *(float4*)&out[O_ROIS + ((long)b * POST + s) * 4] = v;
        out[O_IDX + b * POST + s] = (float)b;
    }
}

// ---------------------------------------------------------------------------
extern "C" void kernel_launch(void* const* d_in, const int* in_sizes, int n_in,
                              void* d_out, int out_size) {
    const float* x   = (const float*)d_in[0];
    const float* w1  = (const float*)d_in[1];
    const float* b1  = (const float*)d_in[2];
    const float* wsc = (const float*)d_in[3];
    const float* bsc = (const float*)d_in[4];
    const float* wlc = (const float*)d_in[5];
    const float* blc = (const float*)d_in[6];
    const int*   ih  = (const int*)d_in[7];
    const int*   iw  = (const int*)d_in[8];
    float* out = (float*)d_out;

    wtrans_k<<<9 * CIN * COUT / 256, 256>>>(w1);
    conv3x3_k<<<dim3(COUT / 256, NB * HH), 256>>>(x, b1);
    heads_k<<<NB * HH * 2, 256>>>(wsc, bsc, wlc, blc, out);
    fg_k<<<NB * MTOT / 256, 256>>>(out);
    decode_k<<<NB * SEG / 256, 256>>>(out, ih, iw);

    bitonic_presort_k<<<NB * SEG / 2048, 1024>>>();
    for (int size = 4096; size <= SEG; size <<= 1) {
        for (int stride = size >> 1; stride >= 2048; stride >>= 1)
            bitonic_global_k<<<NB * SEG / 2 / 256, 256>>>(size, stride);
        bitonic_finish_k<<<NB * SEG / 2048, 1024>>>(size);
    }

    gather_k<<<NB * 2048 / 256, 256>>>();
    nms_mask_k<<<NB * PRE / 4, 128>>>();
    nms_scan_k<<<NB, 32>>>(out);
    (void)in_sizes; (void)n_in; (void)out_size;
}

// round 11
// speedup vs baseline: 1.1612x; 1.1612x over previous
#include <cuda_runtime.h>
#include <math.h>

// ---------------------------------------------------------------------------
// Problem constants (fixed by setup_inputs)
// ---------------------------------------------------------------------------
#define NB    8
#define HH    64
#define WW    64
#define CIN   512
#define COUT  512
#define PIX   4096          // HH*WW
#define NANC  9
#define MTOT  36864         // PIX*NANC
#define SEG   65536         // sort segment (padded)
#define PRE   2000
#define POST  300

// output packing (concatenated float32, return order of reference())
#define O_LOCS   0                    // 8*36864*4  = 1179648
#define O_SCORES 1179648              // 8*36864*2  =  589824
#define O_ROIS   1769472              // 8*300*4    =    9600
#define O_IDX    1779072              // 8*300      =    2400
#define O_ANCH   1781472              // 36864*4    =  147456

typedef unsigned long long u64t;

// Correctly-rounded fp32 exp (immune to fast-math substitution).
__device__ __forceinline__ float exact_expf(float x) {
    return (float)exp((double)x);
}

// Packed fp32x2 helpers (Blackwell). Each half of fma.rn.f32x2 is a full
// IEEE-rn fp32 FMA — bitwise identical to __fmaf_rn on that half.
__device__ __forceinline__ u64t pack2_dup(float v) {
    u64t r; asm("mov.b64 %0, {%1, %2};" : "=l"(r) : "f"(v), "f"(v)); return r;
}
__device__ __forceinline__ void fma2(u64t& d, u64t a, u64t b) {
    asm("fma.rn.f32x2 %0, %1, %2, %0;" : "+l"(d) : "l"(a), "l"(b));
}
__device__ __forceinline__ void unpack2(float& lo, float& hi, u64t v) {
    asm("mov.b64 {%0, %1}, %2;" : "=f"(lo), "=f"(hi) : "l"(v));
}

// ---------------------------------------------------------------------------
// Device scratch (static -> allocation-free)
// ---------------------------------------------------------------------------
__device__ float              g_h[NB * COUT * PIX];        // 64 MB conv output
__device__ float              g_wT[9 * CIN * COUT];        // transposed weights [k][c][o]
__device__ float              g_fg[NB * MTOT];             // fg scores
__device__ float              g_boxes[NB * MTOT * 4];      // decoded boxes
__device__ unsigned long long g_keys[NB * SEG];            // sort keys
__device__ float              g_tb[NB * PRE * 4];          // top-2000 boxes
__device__ unsigned char      g_tvalid[NB * PRE];
__device__ unsigned           g_mask[NB * PRE * 64];       // NMS bitmask rows

// ---------------------------------------------------------------------------
// Weight transpose: wT[k][c][o] = w[o][c][k]. Coalesced writes; ~20us.
// ---------------------------------------------------------------------------
__global__ void wtrans_k(const float* __restrict__ w) {
    long t = (long)blockIdx.x * 256 + threadIdx.x;     // 9*512*512 threads
    int k   = (int)(t / (CIN * COUT));
    int rem = (int)(t - (long)k * CIN * COUT);
    int c   = rem >> 9;
    int o   = rem & 511;
    g_wT[t] = w[(long)o * 4608 + c * 9 + k];
}

// ---------------------------------------------------------------------------
// 3x3 conv (512->512, pad 1) + bias + ReLU, fp32.
// NUMERICS FROZEN (bitwise = R8/R9): per-output single fp32 accumulator,
// IEEE-rn FMA chain strictly ordered (ky, kx, c ascending).
// NEW: accumulators packed as f32x2 over OUTPUT-CHANNEL PAIRS; fma.rn.f32x2
// does both chains at once (2 FMAs/instr -> past the 3-reg FFMA issue floor).
// Block: 128 outch x 64 px (one row). 256 threads, (4 o-pairs) x 4 px tile.
// ---------------------------------------------------------------------------
#define CCH 32
__global__ void __launch_bounds__(256) conv3x3_k(const float* __restrict__ x,
                                                 const float* __restrict__ bias) {
    __shared__ float xs[CCH][68];        // input row slice for current (ky,kx)
    __shared__ float ws[CCH][136];       // [c][outch 0..127], row = 544B (16B mult)

    const int rt  = blockIdx.y;          // n*64 + y
    const int n   = rt >> 6;
    const int y   = rt & 63;
    const int ko0 = blockIdx.x << 7;     // 128 outch per block
    const int tid = threadIdx.x;
    const int tp  = tid & 15;            // pixel group (px0 = tp*4)
    const int to  = tid >> 4;            // outch group (o0 = to*8)
    const int px0 = tp << 2;
    const int o0  = to << 3;

    u64t acc2[4][4];                     // [o-pair][px], halves = (o, o+1)
#pragma unroll
    for (int a = 0; a < 4; a++)
#pragma unroll
        for (int b = 0; b < 4; b++) acc2[a][b] = 0ull;

    const float* xb = x + (long)n * CIN * PIX;

    for (int ky = 0; ky < 3; ky++) {
        int yy = y - 1 + ky;
        bool rowok = (yy >= 0 && yy < 64);
        const float* xrow = xb + yy * 64;
        for (int kx = 0; kx < 3; kx++) {
            const float* wk = g_wT + (ky * 3 + kx) * (CIN * COUT) + ko0;
            for (int c0 = 0; c0 < CIN; c0 += CCH) {
                // stage x: xs[cc][p] = x[c0+cc][yy][p+kx-1] (zero OOB)
                for (int idx = tid; idx < CCH * 64; idx += 256) {
                    int cc = idx >> 6;
                    int p  = idx & 63;
                    int xx = p + kx - 1;
                    float v = 0.f;
                    if (rowok && xx >= 0 && xx < 64)
                        v = xrow[(c0 + cc) * PIX + xx];
                    xs[cc][p] = v;
                }
                // stage w (coalesced float4 from transposed layout): 32c x 128o
                for (int idx = tid; idx < CCH * 32; idx += 256) {
                    int cc = idx >> 5;
                    int o4 = (idx & 31) << 2;
                    float4 wv = *(const float4*)&wk[(c0 + cc) * COUT + o4];
                    *(float4*)&ws[cc][o4] = wv;
                }
                __syncthreads();

#pragma unroll 8
                for (int cc = 0; cc < CCH; cc++) {
                    float4 xv = *(const float4*)&xs[cc][px0];
                    // w pairs: consecutive outch in ws = ready-packed f32x2
                    double2 wd0 = *(const double2*)&ws[cc][o0];      // (o0,o0+1),(o0+2,o0+3)
                    double2 wd1 = *(const double2*)&ws[cc][o0 + 4];  // (o0+4..o0+7)
                    u64t wp[4] = {__double_as_longlong(wd0.x),
                                  __double_as_longlong(wd0.y),
                                  __double_as_longlong(wd1.x),
                                  __double_as_longlong(wd1.y)};
                    u64t xp[4] = {pack2_dup(xv.x), pack2_dup(xv.y),
                                  pack2_dup(xv.z), pack2_dup(xv.w)};
#pragma unroll
                    for (int op = 0; op < 4; op++)
#pragma unroll
                        for (int p = 0; p < 4; p++)
                            fma2(acc2[op][p], wp[op], xp[p]);
                }
                __syncthreads();
            }
        }
    }

#pragma unroll
    for (int op = 0; op < 4; op++) {
        float lo[4], hi[4];
#pragma unroll
        for (int p = 0; p < 4; p++) unpack2(lo[p], hi[p], acc2[op][p]);
        int koA = ko0 + o0 + 2 * op;
        int koB = koA + 1;
        float bA = bias[koA], bB = bias[koB];
        float4 rA, rB;
        rA.x = fmaxf(__fadd_rn(lo[0], bA), 0.f);
        rA.y = fmaxf(__fadd_rn(lo[1], bA), 0.f);
        rA.z = fmaxf(__fadd_rn(lo[2], bA), 0.f);
        rA.w = fmaxf(__fadd_rn(lo[3], bA), 0.f);
        rB.x = fmaxf(__fadd_rn(hi[0], bB), 0.f);
        rB.y = fmaxf(__fadd_rn(hi[1], bB), 0.f);
        rB.z = fmaxf(__fadd_rn(hi[2], bB), 0.f);
        rB.w = fmaxf(__fadd_rn(hi[3], bB), 0.f);
        *(float4*)&g_h[((n * COUT + koA) * HH + y) * WW + px0] = rA;
        *(float4*)&g_h[((n * COUT + koB) * HH + y) * WW + px0] = rB;
    }
}

// ---------------------------------------------------------------------------
// 1x1 heads: serial fp32 FMA over c ascending (NUMERICS FROZEN).
// ---------------------------------------------------------------------------
__global__ void __launch_bounds__(256) heads_k(const float* __restrict__ wsc,
                                               const float* __restrict__ bsc,
                                               const float* __restrict__ wlc,
                                               const float* __restrict__ blc,
                                               float* __restrict__ out) {
    const int bid  = blockIdx.x;         // 8*64*2 = 1024 blocks
    const int n    = bid >> 7;
    const int rem  = bid & 127;
    const int y    = rem >> 1;
    const int x0   = (rem & 1) << 5;
    const int lane = threadIdx.x & 31;
    const int wi   = threadIdx.x >> 5;
    const int ob   = wi * 7;

    float acc[7];
#pragma unroll
    for (int k = 0; k < 7; k++) acc[k] = 0.f;

    const float* hp = g_h + ((long)n * CIN * HH + y) * WW + x0 + lane;
    for (int c = 0; c < CIN; c++) {
        float hv = hp[c * PIX];
#pragma unroll
        for (int k = 0; k < 7; k++) {
            int o = ob + k;
            if (o < 54) {
                float wv = (o < 18) ? wsc[o * 512 + c] : wlc[(o - 18) * 512 + c];
                acc[k] = __fmaf_rn(hv, wv, acc[k]);
            }
        }
    }
    int pix = (n * 64 + y) * 64 + x0 + lane;
#pragma unroll
    for (int k = 0; k < 7; k++) {
        int o = ob + k;
        if (o >= 54) break;
        if (o < 18) out[O_SCORES + (long)pix * 18 + o]        = __fadd_rn(acc[k], bsc[o]);
        else        out[O_LOCS   + (long)pix * 36 + (o - 18)] = __fadd_rn(acc[k], blc[o - 18]);
    }
}

// softmax over score pairs -> fg score
__global__ void fg_k(const float* __restrict__ out) {
    int t = blockIdx.x * 256 + threadIdx.x;
    float s0 = out[O_SCORES + (long)t * 2];
    float s1 = out[O_SCORES + (long)t * 2 + 1];
    float m  = fmaxf(s0, s1);
    float e0 = exact_expf(__fsub_rn(s0, m));
    float e1 = exact_expf(__fsub_rn(s1, m));
    g_fg[t]  = __fdiv_rn(e1, __fadd_rn(e0, e1));
}

// ---------------------------------------------------------------------------
// anchors + box decode + clip + min-size mask + sort-key build
// meshgrid 'ij' transpose: yshift=(p%64)*16, xshift=(p/64)*16
// ---------------------------------------------------------------------------
__global__ void decode_k(float* __restrict__ out, const int* __restrict__ pih,
                         const int* __restrict__ piw) {
    int t = blockIdx.x * 256 + threadIdx.x;
    int b = t >> 16;
    int i = t & (SEG - 1);
    if (i >= MTOT) { g_keys[t] = 0xFFFFFFFFFFFFFFFFull; return; }

    int m   = i;
    int pxl = m / 9;
    int a   = m - pxl * 9;
    float ys  = (float)((pxl & 63) * 16);
    float xsh = (float)((pxl >> 6) * 16);

    const double RR[3] = {0.5, 1.0, 2.0};
    const double SS[3] = {8.0, 16.0, 32.0};
    int ridx = a / 3, sidx = a - ridx * 3;
    double hh = 16.0 * SS[sidx] * sqrt(RR[ridx]);
    double ww = 16.0 * SS[sidx] * sqrt(1.0 / RR[ridx]);
    float ay1 = (float)(8.0 - hh * 0.5);
    float ax1 = (float)(8.0 - ww * 0.5);
    float ay2 = (float)(8.0 + hh * 0.5);
    float ax2 = (float)(8.0 + ww * 0.5);

    float A0 = __fadd_rn(ay1, ys), A1 = __fadd_rn(ax1, xsh);
    float A2 = __fadd_rn(ay2, ys), A3 = __fadd_rn(ax2, xsh);
    if (b == 0) {
        float4 av = make_float4(A0, A1, A2, A3);
        *(float4*)&out[O_ANCH + (long)m * 4] = av;
    }

    float4 L = *(const float4*)&out[O_LOCS + ((long)b * MTOT + m) * 4];
    float ah  = __fsub_rn(A2, A0);
    float aw  = __fsub_rn(A3, A1);
    float acy = __fadd_rn(A0, __fmul_rn(0.5f, ah));
    float acx = __fadd_rn(A1, __fmul_rn(0.5f, aw));
    float cy  = __fadd_rn(__fmul_rn(L.x, ah), acy);
    float cx  = __fadd_rn(__fmul_rn(L.y, aw), acx);
    float bh  = __fmul_rn(exact_expf(L.z), ah);
    float bw  = __fmul_rn(exact_expf(L.w), aw);

    int vih = pih[0], viw = piw[0];
    float fh = (vih > 0 && vih < (1 << 20)) ? (float)vih : __int_as_float(vih);
    float fw = (viw > 0 && viw < (1 << 20)) ? (float)viw : __int_as_float(viw);

    float y1 = fminf(fmaxf(__fsub_rn(cy, __fmul_rn(0.5f, bh)), 0.f), fh);
    float x1 = fminf(fmaxf(__fsub_rn(cx, __fmul_rn(0.5f, bw)), 0.f), fw);
    float y2 = fminf(fmaxf(__fadd_rn(cy, __fmul_rn(0.5f, bh)), 0.f), fh);
    float x2 = fminf(fmaxf(__fadd_rn(cx, __fmul_rn(0.5f, bw)), 0.f), fw);
    float4 bx = make_float4(y1, x1, y2, x2);
    *(float4*)&g_boxes[((long)b * MTOT + m) * 4] = bx;

    float hs  = __fsub_rn(y2, y1);
    float wsz = __fsub_rn(x2, x1);
    bool valid = (hs >= 16.f) && (wsz >= 16.f);
    unsigned dk;
    if (valid) {
        float sc = g_fg[b * MTOT + m];
        unsigned ub  = __float_as_uint(sc);
        unsigned asc = (ub & 0x80000000u) ? ~ub : (ub | 0x80000000u);
        dk = ~asc;
    } else {
        dk = 0xFF800000u;
    }
    g_keys[t] = ((unsigned long long)dk << 32) | (unsigned)m;
}

// ---------------------------------------------------------------------------
// bitonic sort of 8 segments of 65536 u64 keys, ascending
// ---------------------------------------------------------------------------
__global__ void __launch_bounds__(1024) bitonic_presort_k() {
    __shared__ unsigned long long s[2048];
    int  t     = threadIdx.x;
    long base  = (long)blockIdx.x * 2048;
    int  lbase = (blockIdx.x & 31) * 2048;
    s[t] = g_keys[base + t];
    s[t + 1024] = g_keys[base + t + 1024];
    __syncthreads();
    for (int size = 2; size <= 2048; size <<= 1) {
        for (int stride = size >> 1; stride > 0; stride >>= 1) {
            int pos = 2 * t - (t & (stride - 1));
            bool asc = (((lbase + pos) & size) == 0);
            unsigned long long a = s[pos], b = s[pos + stride];
            if ((a > b) == asc) { s[pos] = b; s[pos + stride] = a; }
            __syncthreads();
        }
    }
    g_keys[base + t] = s[t];
    g_keys[base + t + 1024] = s[t + 1024];
}

__global__ void bitonic_global_k(int size, int stride) {
    int t   = blockIdx.x * 256 + threadIdx.x;
    int seg = t >> 15;
    int lt  = t & 32767;
    int pos = 2 * lt - (lt & (stride - 1));
    long i  = ((long)seg << 16) + pos;
    long j  = i + stride;
    bool asc = ((pos & size) == 0);
    unsigned long long a = g_keys[i], b = g_keys[j];
    if ((a > b) == asc) { g_keys[i] = b; g_keys[j] = a; }
}

__global__ void __launch_bounds__(1024) bitonic_finish_k(int size) {
    __shared__ unsigned long long s[2048];
    int  t     = threadIdx.x;
    long base  = (long)blockIdx.x * 2048;
    int  lbase = (blockIdx.x & 31) * 2048;
    bool asc   = ((lbase & size) == 0);
    s[t] = g_keys[base + t];
    s[t + 1024] = g_keys[base + t + 1024];
    __syncthreads();
    for (int stride = 1024; stride > 0; stride >>= 1) {
        int pos = 2 * t - (t & (stride - 1));
        unsigned long long a = s[pos], b = s[pos + stride];
        if ((a > b) == asc) { s[pos] = b; s[pos + stride] = a; }
        __syncthreads();
    }
    g_keys[base + t] = s[t];
    g_keys[base + t + 1024] = s[t + 1024];
}

// gather top-2000 per batch
__global__ void gather_k() {
    int t = blockIdx.x * 256 + threadIdx.x;
    int b = t >> 11;
    int i = t & 2047;
    if (i >= PRE) return;
    unsigned long long key = g_keys[b * SEG + i];
    unsigned idx = (unsigned)(key & 0xFFFFFFFFull);
    bool valid   = (unsigned)(key >> 32) < 0xFF800000u;
    float4 bx = *(const float4*)&g_boxes[((long)b * MTOT + idx) * 4];
    *(float4*)&g_tb[((long)b * PRE + i) * 4] = bx;
    g_tvalid[b * PRE + i] = valid ? 1 : 0;
}

// NMS bitmask: one warp per (b, i) (unfused IEEE fp32 IoU)
__global__ void nms_mask_k() {
    int wid  = blockIdx.x * 4 + (threadIdx.x >> 5);
    int lane = threadIdx.x & 31;
    int b = wid / PRE;
    int i = wid - b * PRE;
    float4 bi = *(const float4*)&g_tb[((long)b * PRE + i) * 4];
    float ai = __fmul_rn(__fsub_rn(bi.z, bi.x), __fsub_rn(bi.w, bi.y));
    unsigned* mrow = g_mask + ((long)b * PRE + i) * 64;
    for (int w = 0; w < 63; w++) {
        int j = w * 32 + lane;
        bool pred = false;
        if (j < PRE) {
            float4 bj = *(const float4*)&g_tb[((long)b * PRE + j) * 4];
            float aj = __fmul_rn(__fsub_rn(bj.z, bj.x), __fsub_rn(bj.w, bj.y));
            float ty = fmaxf(bi.x, bj.x), tx = fmaxf(bi.y, bj.y);
            float by = fminf(bi.z, bj.z), bx = fminf(bi.w, bj.w);
            float ihh = fmaxf(__fsub_rn(by, ty), 0.f);
            float iww = fmaxf(__fsub_rn(bx, tx), 0.f);
            float inter = __fmul_rn(ihh, iww);
            float denom = __fadd_rn(__fsub_rn(__fadd_rn(ai, aj), inter), 1e-10f);
            float iou = __fdiv_rn(inter, denom);
            pred = iou > 0.7f;
        }
        unsigned mword = __ballot_sync(0xFFFFFFFFu, pred);
        if (lane == 0) mrow[w] = mword;
    }
    if (lane == 0) mrow[63] = 0u;
}

// sequential greedy NMS scan (one warp per batch) + output rois/indices
__global__ void nms_scan_k(float* __restrict__ out) {
    int b = blockIdx.x;
    int lane = threadIdx.x;
    __shared__ unsigned rem[64];
    __shared__ int keptS[POST];
    __shared__ int nkS;
    rem[lane] = 0u; rem[lane + 32] = 0u;
    if (lane == 0) nkS = 0;
    __syncwarp();

    const unsigned char* valid = g_tvalid + b * PRE;
    const unsigned* maskb = g_mask + (long)b * PRE * 64;
    int nk = 0;
    for (int i = 0; i < PRE; i++) {
        int keep = 0;
        if (lane == 0)
            keep = valid[i] && !((rem[i >> 5] >> (i & 31)) & 1u);
        keep = __shfl_sync(0xFFFFFFFFu, keep, 0);
        if (keep) {
            if (lane == 0) keptS[nk] = i;
            nk++;
            if (nk >= POST) break;
            rem[2 * lane]     |= maskb[i * 64 + 2 * lane];
            rem[2 * lane + 1] |= maskb[i * 64 + 2 * lane + 1];
            __syncwarp();
        }
    }
    if (lane == 0) nkS = nk;
    __syncwarp();
    nk = nkS;
    for (int s = lane; s < POST; s += 32) {
        float4 v = make_float4(0.f, 0.f, 0.f, 0.f);
        if (s < nk) {
            int ii = keptS[s];
            v = *(const float4*)&g_tb[((long)b * PRE + ii) * 4];
        }
        *(float4*)&out[O_ROIS + ((long)b * POST + s) * 4] = v;
        out[O_IDX + b * POST + s] = (float)b;
    }
}

// ---------------------------------------------------------------------------
extern "C" void kernel_launch(void* const* d_in, const int* in_sizes, int n_in,
                              void* d_out, int out_size) {
    const float* x   = (const float*)d_in[0];
    const float* w1  = (const float*)d_in[1];
    const float* b1  = (const float*)d_in[2];
    const float* wsc = (const float*)d_in[3];
    const float* bsc = (const float*)d_in[4];
    const float* wlc = (const float*)d_in[5];
    const float* blc = (const float*)d_in[6];
    const int*   ih  = (const int*)d_in[7];
    const int*   iw  = (const int*)d_in[8];
    float* out = (float*)d_out;

    wtrans_k<<<9 * CIN * COUT / 256, 256>>>(w1);
    conv3x3_k<<<dim3(COUT / 128, NB * HH), 256>>>(x, b1);
    heads_k<<<NB * HH * 2, 256>>>(wsc, bsc, wlc, blc, out);
    fg_k<<<NB * MTOT / 256, 256>>>(out);
    decode_k<<<NB * SEG / 256, 256>>>(out, ih, iw);

    bitonic_presort_k<<<NB * SEG / 2048, 1024>>>();
    for (int size = 4096; size <= SEG; size <<= 1) {
        for (int stride = size >> 1; stride >= 2048; stride >>= 1)
            bitonic_global_k<<<NB * SEG / 2 / 256, 256>>>(size, stride);
        bitonic_finish_k<<<NB * SEG / 2048, 1024>>>(size);
    }

    gather_k<<<NB * 2048 / 256, 256>>>();
    nms_mask_k<<<NB * PRE / 4, 128>>>();
    nms_scan_k<<<NB, 32>>>(out);
    (void)in_sizes; (void)n_in; (void)out_size;
}